// round 1
// baseline (speedup 1.0000x reference)
#include <cuda_runtime.h>

#define H 512
#define W 512
#define HW (H*W)
#define NB 2
#define NC 21
#define NPIX (NB*HW)
#define NTAP 25

// ping-pong q buffers + combined coefficient field (scratch: __device__ globals, no allocs)
__device__ float g_qA[NB*NC*HW];
__device__ float g_qB[NB*NC*HW];
__device__ float g_wc[NTAP*NB*HW];   // SoA: [tap][b][y][x]

__device__ __forceinline__ int reflect_idx(int i, int n) {
    if (i < 0) i = -i;
    if (i >= n) i = 2*n - 2 - i;
    return i;
}

// ---------------------------------------------------------------------------
// Kernel 1: q0 = softmax(unary) over channel axis
// ---------------------------------------------------------------------------
__global__ void __launch_bounds__(256) init_softmax(const float* __restrict__ unary,
                                                    float* __restrict__ q) {
    int idx = blockIdx.x * 256 + threadIdx.x;
    if (idx >= NPIX) return;
    int b = idx / HW, pix = idx % HW;
    const float* u = unary + (size_t)b * NC * HW + pix;
    float e[NC];
    float s = 0.f;
#pragma unroll
    for (int c = 0; c < NC; c++) { e[c] = __expf(u[c*HW]); s += e[c]; }
    float inv = 1.f / s;
    float* qo = q + (size_t)b * NC * HW + pix;
#pragma unroll
    for (int c = 0; c < NC; c++) qo[c*HW] = e[c] * inv;
}

// ---------------------------------------------------------------------------
// Kernel 2: combined coefficients
//   Wc[t] = g2d[t] + w_rgb[t]/sum(w_rgb) + w_edge[t]/sum(w_edge)
// sigma_color = 0.5 for both filters -> exponent factor -2*d*d
// sigma_space = 5.0 -> space = exp(-x^2/50) (normalization cancels)
// gaussian blur sigma = 0.5 -> g1 = exp(-2 x^2), normalized
// ---------------------------------------------------------------------------
__global__ void __launch_bounds__(256) compute_weights(const float* __restrict__ image,
                                                       const float* __restrict__ edges) {
    __shared__ float sg[4][12][36];   // 3 rgb planes + 1 edge plane, tile 32x8 + halo 2
    int tx = threadIdx.x, ty = threadIdx.y;
    int b = blockIdx.z;
    int x0 = blockIdx.x * 32, y0 = blockIdx.y * 8;
    int tid = ty * 32 + tx;

    for (int idx = tid; idx < 4*12*36; idx += 256) {
        int ch = idx / (12*36);
        int r  = idx % (12*36);
        int ry = r / 36, sx = r % 36;
        int gy = reflect_idx(y0 + ry - 2, H);
        int gx = reflect_idx(x0 + sx - 2, W);
        float v;
        if (ch < 3) v = image[((size_t)(b*3 + ch))*HW + gy*W + gx];
        else        v = edges[(size_t)b*HW + gy*W + gx];
        sg[ch][ry][sx] = v;
    }
    __syncthreads();

    float sp[5], g2[5];
    {
        float s = 0.f;
#pragma unroll
        for (int i = 0; i < 5; i++) {
            float x = (float)(i - 2);
            sp[i] = __expf(-x*x * 0.02f);    // spatial, sigma_space=5 (unnormalized: cancels)
            float g = __expf(-2.f * x*x);    // blur kernel, sigma=0.5
            g2[i] = g; s += g;
        }
        float inv = 1.f / s;
#pragma unroll
        for (int i = 0; i < 5; i++) g2[i] *= inv;
    }

    int ry = ty + 2, rx = tx + 2;
    float cr = sg[0][ry][rx], cg = sg[1][ry][rx], cb = sg[2][ry][rx], ce = sg[3][ry][rx];

    float wr[NTAP], we[NTAP];
    float sr = 0.f, se = 0.f;
#pragma unroll
    for (int dy = 0; dy < 5; dy++) {
#pragma unroll
        for (int dx = 0; dx < 5; dx++) {
            int t = dy*5 + dx;
            float d = fabsf(sg[0][ry+dy-2][rx+dx-2] - cr)
                    + fabsf(sg[1][ry+dy-2][rx+dx-2] - cg)
                    + fabsf(sg[2][ry+dy-2][rx+dx-2] - cb);
            float s2 = sp[dy] * sp[dx];
            float w  = s2 * __expf(-2.f * d * d);
            wr[t] = w; sr += w;
            float de = fabsf(sg[3][ry+dy-2][rx+dx-2] - ce);
            float w2 = s2 * __expf(-2.f * de * de);
            we[t] = w2; se += w2;
        }
    }
    float isr = 1.f / sr, ise = 1.f / se;
    int pix = b*HW + (y0 + ty)*W + (x0 + tx);
#pragma unroll
    for (int dy = 0; dy < 5; dy++) {
#pragma unroll
        for (int dx = 0; dx < 5; dx++) {
            int t = dy*5 + dx;
            g_wc[t*(NB*HW) + pix] = g2[dy]*g2[dx] + wr[t]*isr + we[t]*ise;
        }
    }
}

// ---------------------------------------------------------------------------
// Kernel 3: one CRF iteration, fully fused:
//   F_c = 25-tap stencil(q_in, Wc);  q_out = softmax(unary - F)
// Tile: 64x8 pixels, block (32,8), 2 px/thread in x.
// ---------------------------------------------------------------------------
#define TX 64
#define TY 8
#define SW (TX + 4)    // 68
#define SH (TY + 4)    // 12
#define SMEMB (NC * SH * SW * 4)

__global__ void __launch_bounds__(256, 2) crf_iter(const float* __restrict__ unary,
                                                   const float* __restrict__ qin,
                                                   float* __restrict__ qout) {
    extern __shared__ float sq[];   // [NC][SH][SW]
    int tx = threadIdx.x, ty = threadIdx.y;
    int b = blockIdx.z;
    int x0 = blockIdx.x * TX, y0 = blockIdx.y * TY;
    int tid = ty * 32 + tx;

    const float* qb = qin + (size_t)b * NC * HW;
    for (int idx = tid; idx < NC*SH*SW; idx += 256) {
        int c  = idx / (SH*SW);
        int r  = idx % (SH*SW);
        int ry = r / SW, sx = r % SW;
        int gy = reflect_idx(y0 + ry - 2, H);
        int gx = reflect_idx(x0 + sx - 2, W);
        sq[idx] = qb[c*HW + gy*W + gx];
    }
    __syncthreads();

    int xl  = tx * 2;            // local x of first pixel; smem x index of (gx-2) == xl
    int gx0 = x0 + xl;
    int gy  = y0 + ty;

    float acc0[NC], acc1[NC];
#pragma unroll
    for (int c = 0; c < NC; c++) { acc0[c] = 0.f; acc1[c] = 0.f; }

    int wbase = b*HW + gy*W + gx0;
#pragma unroll
    for (int dy = 0; dy < 5; dy++) {
        float c0[5], c1[5];
#pragma unroll
        for (int dx = 0; dx < 5; dx++) {
            float2 cc = *reinterpret_cast<const float2*>(&g_wc[(dy*5 + dx)*(NB*HW) + wbase]);
            c0[dx] = cc.x; c1[dx] = cc.y;
        }
        const float* rowb = &sq[(ty + dy)*SW + xl];
#pragma unroll
        for (int c = 0; c < NC; c++) {
            const float* rp = rowb + c*(SH*SW);
            float2 v0 = *reinterpret_cast<const float2*>(rp);
            float2 v1 = *reinterpret_cast<const float2*>(rp + 2);
            float2 v2 = *reinterpret_cast<const float2*>(rp + 4);
            acc0[c] += c0[0]*v0.x + c0[1]*v0.y + c0[2]*v1.x + c0[3]*v1.y + c0[4]*v2.x;
            acc1[c] += c1[0]*v0.y + c1[1]*v1.x + c1[2]*v1.y + c1[3]*v2.x + c1[4]*v2.y;
        }
    }

    // q_out = softmax(unary - F)   (softmax shift-invariance kills _compat colsum)
    const float* ub = unary + (size_t)b * NC * HW + gy*W + gx0;
    float s0 = 0.f, s1 = 0.f;
#pragma unroll
    for (int c = 0; c < NC; c++) {
        float2 u = *reinterpret_cast<const float2*>(ub + c*HW);
        float e0 = __expf(u.x - acc0[c]);
        float e1 = __expf(u.y - acc1[c]);
        acc0[c] = e0; acc1[c] = e1;
        s0 += e0; s1 += e1;
    }
    float i0 = 1.f / s0, i1 = 1.f / s1;
    float* qo = qout + (size_t)b * NC * HW + gy*W + gx0;
#pragma unroll
    for (int c = 0; c < NC; c++) {
        float2 o; o.x = acc0[c]*i0; o.y = acc1[c]*i1;
        *reinterpret_cast<float2*>(qo + c*HW) = o;
    }
}

// ---------------------------------------------------------------------------
extern "C" void kernel_launch(void* const* d_in, const int* in_sizes, int n_in,
                              void* d_out, int out_size) {
    // identify inputs by element count (robust to ordering)
    const float *unary = nullptr, *image = nullptr, *edges = nullptr;
    for (int i = 0; i < n_in; i++) {
        if      (in_sizes[i] == NB*NC*HW) unary = (const float*)d_in[i];
        else if (in_sizes[i] == NB*3*HW)  image = (const float*)d_in[i];
        else if (in_sizes[i] == NB*HW)    edges = (const float*)d_in[i];
    }
    float* out = (float*)d_out;

    float *qA = nullptr, *qB = nullptr;
    cudaGetSymbolAddress((void**)&qA, g_qA);
    cudaGetSymbolAddress((void**)&qB, g_qB);

    cudaFuncSetAttribute(crf_iter, cudaFuncAttributeMaxDynamicSharedMemorySize, SMEMB);

    init_softmax<<<(NPIX + 255)/256, 256>>>(unary, qA);
    compute_weights<<<dim3(W/32, H/8, NB), dim3(32, 8)>>>(image, edges);

    dim3 gi(W/TX, H/TY, NB), bi(32, 8);
    const float* cur = qA;
    for (int it = 0; it < 10; it++) {
        float* dst = (it == 9) ? out : ((cur == qA) ? qB : qA);
        crf_iter<<<gi, bi, SMEMB>>>(unary, cur, dst);
        cur = dst;
    }
}

// round 3
// speedup vs baseline: 1.2189x; 1.2189x over previous
#include <cuda_runtime.h>
#include <cuda_fp16.h>
#include <cstdint>

#define H 512
#define W 512
#define HW (H*W)
#define NB 2
#define NC 21
#define NPIX (NB*HW)
#define NTAP 25

// ping-pong q buffers + combined coefficient field (fp16) — __device__ scratch, no allocs
__device__ float  g_qA[NB*NC*HW];
__device__ float  g_qB[NB*NC*HW];
__device__ __half g_wch[NTAP*NB*HW];   // SoA: [tap][b][y][x], fp16

__device__ __forceinline__ int reflect_idx(int i, int n) {
    if (i < 0) i = -i;
    if (i >= n) i = 2*n - 2 - i;
    return i;
}

// ---------------------------------------------------------------------------
// Kernel 1: q0 = softmax(unary) over channel axis
// ---------------------------------------------------------------------------
__global__ void __launch_bounds__(256) init_softmax(const float* __restrict__ unary,
                                                    float* __restrict__ q) {
    int idx = blockIdx.x * 256 + threadIdx.x;
    if (idx >= NPIX) return;
    int b = idx / HW, pix = idx % HW;
    const float* u = unary + (size_t)b * NC * HW + pix;
    float e[NC];
    float s = 0.f;
#pragma unroll
    for (int c = 0; c < NC; c++) { e[c] = __expf(u[c*HW]); s += e[c]; }
    float inv = 1.f / s;
    float* qo = q + (size_t)b * NC * HW + pix;
#pragma unroll
    for (int c = 0; c < NC; c++) qo[c*HW] = e[c] * inv;
}

// ---------------------------------------------------------------------------
// Kernel 2: combined coefficients (fp16 output)
//   Wc[t] = g2d[t] + w_rgb[t]/sum(w_rgb) + w_edge[t]/sum(w_edge)
// ---------------------------------------------------------------------------
__global__ void __launch_bounds__(256) compute_weights(const float* __restrict__ image,
                                                       const float* __restrict__ edges) {
    __shared__ float sg[4][12][36];   // 3 rgb planes + 1 edge plane, tile 32x8 + halo 2
    int tx = threadIdx.x, ty = threadIdx.y;
    int b = blockIdx.z;
    int x0 = blockIdx.x * 32, y0 = blockIdx.y * 8;
    int tid = ty * 32 + tx;

    for (int idx = tid; idx < 4*12*36; idx += 256) {
        int ch = idx / (12*36);
        int r  = idx % (12*36);
        int ry = r / 36, sx = r % 36;
        int gy = reflect_idx(y0 + ry - 2, H);
        int gx = reflect_idx(x0 + sx - 2, W);
        float v;
        if (ch < 3) v = image[((size_t)(b*3 + ch))*HW + gy*W + gx];
        else        v = edges[(size_t)b*HW + gy*W + gx];
        sg[ch][ry][sx] = v;
    }
    __syncthreads();

    float sp[5], g2[5];
    {
        float s = 0.f;
#pragma unroll
        for (int i = 0; i < 5; i++) {
            float x = (float)(i - 2);
            sp[i] = __expf(-x*x * 0.02f);    // spatial, sigma_space=5 (unnormalized: cancels)
            float g = __expf(-2.f * x*x);    // blur kernel, sigma=0.5
            g2[i] = g; s += g;
        }
        float inv = 1.f / s;
#pragma unroll
        for (int i = 0; i < 5; i++) g2[i] *= inv;
    }

    int ry = ty + 2, rx = tx + 2;
    float cr = sg[0][ry][rx], cg = sg[1][ry][rx], cb = sg[2][ry][rx], ce = sg[3][ry][rx];

    float wr[NTAP], we[NTAP];
    float sr = 0.f, se = 0.f;
#pragma unroll
    for (int dy = 0; dy < 5; dy++) {
#pragma unroll
        for (int dx = 0; dx < 5; dx++) {
            int t = dy*5 + dx;
            float d = fabsf(sg[0][ry+dy-2][rx+dx-2] - cr)
                    + fabsf(sg[1][ry+dy-2][rx+dx-2] - cg)
                    + fabsf(sg[2][ry+dy-2][rx+dx-2] - cb);
            float s2 = sp[dy] * sp[dx];
            float w  = s2 * __expf(-2.f * d * d);
            wr[t] = w; sr += w;
            float de = fabsf(sg[3][ry+dy-2][rx+dx-2] - ce);
            float w2 = s2 * __expf(-2.f * de * de);
            we[t] = w2; se += w2;
        }
    }
    float isr = 1.f / sr, ise = 1.f / se;
    int pix = b*HW + (y0 + ty)*W + (x0 + tx);
#pragma unroll
    for (int dy = 0; dy < 5; dy++) {
#pragma unroll
        for (int dx = 0; dx < 5; dx++) {
            int t = dy*5 + dx;
            g_wch[t*(NB*HW) + pix] = __float2half(g2[dy]*g2[dx] + wr[t]*isr + we[t]*ise);
        }
    }
}

// ---------------------------------------------------------------------------
// Kernel 3: one CRF iteration, fully fused:
//   F_c = 25-tap stencil(q_in, Wc);  q_out = softmax(unary - F)
// Tile: 64x16 pixels, block (32,16) = 512 thr, 2 px/thread in x.
// Fill: incremental indexing (no div/mod), float2 granularity, cp.async for
// x-interior blocks; reflect-scalar path only for x-boundary block columns.
// ---------------------------------------------------------------------------
#define TX 64
#define TY 16
#define SW 68            // TX + 4
#define SH 20            // TY + 4
#define NROW (NC*SH)     // 420 rows of 68 floats
#define NF2  (NROW*34)   // 14280 float2 elements
#define NFILL 28         // ceil(NF2/512)
#define SMEMB (NC * SH * SW * 4)   // 114240 B

__global__ void __launch_bounds__(512, 1) crf_iter(const float* __restrict__ unary,
                                                   const float* __restrict__ qin,
                                                   float* __restrict__ qout) {
    extern __shared__ float sq[];   // [NC][SH][SW]
    int tx = threadIdx.x, ty = threadIdx.y;
    int b = blockIdx.z;
    int x0 = blockIdx.x * TX, y0 = blockIdx.y * TY;
    int tid = ty * 32 + tx;

    const float* qb = qin + (size_t)b * NC * HW;

    uint32_t sbase;
    asm("{ .reg .u64 t; cvta.to.shared.u64 t, %1; cvt.u32.u64 %0, t; }"
        : "=r"(sbase) : "l"(sq));

    bool xInt = (blockIdx.x != 0) && (blockIdx.x != gridDim.x - 1);

    // incremental (col2, ry, c) bookkeeping: idx += 512 == +15 rows + 2 cols
    int idx  = tid;
    int col2 = idx % 34;
    int rowi = idx / 34;
    int ry   = rowi % SH;
    int c    = rowi / SH;

    if (xInt) {
#pragma unroll
        for (int it = 0; it < NFILL; it++) {
            if (idx < NF2) {
                int gy = reflect_idx(y0 + ry - 2, H);
                int gx = x0 + col2*2 - 2;
                const float* src = qb + c*HW + gy*W + gx;
                uint32_t dst = sbase + (uint32_t)tid*8u + (uint32_t)it*4096u;
                asm volatile("cp.async.ca.shared.global [%0], [%1], 8;"
                             :: "r"(dst), "l"(src));
            }
            col2 += 2; if (col2 >= 34) { col2 -= 34; ry++; }
            ry += 15;
            if (ry >= SH) { ry -= SH; c++; }
            idx += 512;
        }
        asm volatile("cp.async.commit_group;");
        asm volatile("cp.async.wait_group 0;" ::: "memory");
    } else {
#pragma unroll 4
        for (int it = 0; it < NFILL; it++) {
            if (idx < NF2) {
                int gy  = reflect_idx(y0 + ry - 2, H);
                int gxa = reflect_idx(x0 + col2*2 - 2, W);
                int gxb = reflect_idx(x0 + col2*2 - 1, W);
                const float* src = qb + c*HW + gy*W;
                float2 v; v.x = src[gxa]; v.y = src[gxb];
                reinterpret_cast<float2*>(sq)[idx] = v;
            }
            col2 += 2; if (col2 >= 34) { col2 -= 34; ry++; }
            ry += 15;
            if (ry >= SH) { ry -= SH; c++; }
            idx += 512;
        }
    }
    __syncthreads();

    int xl  = tx * 2;            // local x of first pixel; smem x index of (gx-2) == xl
    int gx0 = x0 + xl;
    int gy  = y0 + ty;

    float acc0[NC], acc1[NC];
#pragma unroll
    for (int cc = 0; cc < NC; cc++) { acc0[cc] = 0.f; acc1[cc] = 0.f; }

    int wbase = b*HW + gy*W + gx0;
#pragma unroll
    for (int dy = 0; dy < 5; dy++) {
        float c0[5], c1[5];
#pragma unroll
        for (int dx = 0; dx < 5; dx++) {
            __half2 h = *reinterpret_cast<const __half2*>(&g_wch[(dy*5 + dx)*(NB*HW) + wbase]);
            float2 cc = __half22float2(h);
            c0[dx] = cc.x; c1[dx] = cc.y;
        }
        const float* rowb = &sq[(ty + dy)*SW + xl];
#pragma unroll
        for (int ch = 0; ch < NC; ch++) {
            const float* rp = rowb + ch*(SH*SW);
            float2 v0 = *reinterpret_cast<const float2*>(rp);
            float2 v1 = *reinterpret_cast<const float2*>(rp + 2);
            float2 v2 = *reinterpret_cast<const float2*>(rp + 4);
            acc0[ch] += c0[0]*v0.x + c0[1]*v0.y + c0[2]*v1.x + c0[3]*v1.y + c0[4]*v2.x;
            acc1[ch] += c1[0]*v0.y + c1[1]*v1.x + c1[2]*v1.y + c1[3]*v2.x + c1[4]*v2.y;
        }
    }

    // q_out = softmax(unary - F)   (softmax shift-invariance kills _compat colsum)
    const float* ub = unary + (size_t)b * NC * HW + gy*W + gx0;
    float s0 = 0.f, s1 = 0.f;
#pragma unroll
    for (int ch = 0; ch < NC; ch++) {
        float2 u = *reinterpret_cast<const float2*>(ub + ch*HW);
        float e0 = __expf(u.x - acc0[ch]);
        float e1 = __expf(u.y - acc1[ch]);
        acc0[ch] = e0; acc1[ch] = e1;
        s0 += e0; s1 += e1;
    }
    float i0 = 1.f / s0, i1 = 1.f / s1;
    float* qo = qout + (size_t)b * NC * HW + gy*W + gx0;
#pragma unroll
    for (int ch = 0; ch < NC; ch++) {
        float2 o; o.x = acc0[ch]*i0; o.y = acc1[ch]*i1;
        *reinterpret_cast<float2*>(qo + ch*HW) = o;
    }
}

// ---------------------------------------------------------------------------
extern "C" void kernel_launch(void* const* d_in, const int* in_sizes, int n_in,
                              void* d_out, int out_size) {
    // identify inputs by element count (robust to ordering)
    const float *unary = nullptr, *image = nullptr, *edges = nullptr;
    for (int i = 0; i < n_in; i++) {
        if      (in_sizes[i] == NB*NC*HW) unary = (const float*)d_in[i];
        else if (in_sizes[i] == NB*3*HW)  image = (const float*)d_in[i];
        else if (in_sizes[i] == NB*HW)    edges = (const float*)d_in[i];
    }
    float* out = (float*)d_out;

    float *qA = nullptr, *qB = nullptr;
    cudaGetSymbolAddress((void**)&qA, g_qA);
    cudaGetSymbolAddress((void**)&qB, g_qB);

    cudaFuncSetAttribute(crf_iter, cudaFuncAttributeMaxDynamicSharedMemorySize, SMEMB);

    init_softmax<<<(NPIX + 255)/256, 256>>>(unary, qA);
    compute_weights<<<dim3(W/32, H/8, NB), dim3(32, 8)>>>(image, edges);

    dim3 gi(W/TX, H/TY, NB), bi(32, 16);
    const float* cur = qA;
    for (int it = 0; it < 10; it++) {
        float* dst = (it == 9) ? out : ((cur == qA) ? qB : qA);
        crf_iter<<<gi, bi, SMEMB>>>(unary, cur, dst);
        cur = dst;
    }
}

// round 4
// speedup vs baseline: 1.4617x; 1.1992x over previous
#include <cuda_runtime.h>
#include <cuda_fp16.h>
#include <cstdint>

#define H 512
#define W 512
#define HW (H*W)
#define NB 2
#define NC 21
#define NPIX (NB*HW)
#define NTAP 25

// ping-pong q buffers (fp16) + combined coefficient field (fp16)
__device__ __half g_qA[NB*NC*HW];
__device__ __half g_qB[NB*NC*HW];
__device__ __half g_wch[NTAP*NB*HW];   // SoA: [tap][b][y][x], fp16

__device__ __forceinline__ int reflect_idx(int i, int n) {
    if (i < 0) i = -i;
    if (i >= n) i = 2*n - 2 - i;
    return i;
}

// ---------------------------------------------------------------------------
// Kernel 1: q0 = softmax(unary), stored fp16
// ---------------------------------------------------------------------------
__global__ void __launch_bounds__(256) init_softmax(const float* __restrict__ unary,
                                                    __half* __restrict__ q) {
    int idx = blockIdx.x * 256 + threadIdx.x;
    if (idx >= NPIX) return;
    int b = idx / HW, pix = idx % HW;
    const float* u = unary + (size_t)b * NC * HW + pix;
    float e[NC];
    float s = 0.f;
#pragma unroll
    for (int c = 0; c < NC; c++) { e[c] = __expf(u[c*HW]); s += e[c]; }
    float inv = 1.f / s;
    __half* qo = q + (size_t)b * NC * HW + pix;
#pragma unroll
    for (int c = 0; c < NC; c++) qo[c*HW] = __float2half(e[c] * inv);
}

// ---------------------------------------------------------------------------
// Kernel 2: combined coefficients (fp16 output)
//   Wc[t] = g2d[t] + w_rgb[t]/sum(w_rgb) + w_edge[t]/sum(w_edge)
// ---------------------------------------------------------------------------
__global__ void __launch_bounds__(256) compute_weights(const float* __restrict__ image,
                                                       const float* __restrict__ edges) {
    __shared__ float sg[4][12][36];   // rgb + edge, tile 32x8 + halo 2
    int tx = threadIdx.x, ty = threadIdx.y;
    int b = blockIdx.z;
    int x0 = blockIdx.x * 32, y0 = blockIdx.y * 8;
    int tid = ty * 32 + tx;

    for (int idx = tid; idx < 4*12*36; idx += 256) {
        int ch = idx / (12*36);
        int r  = idx % (12*36);
        int ry = r / 36, sx = r % 36;
        int gy = reflect_idx(y0 + ry - 2, H);
        int gx = reflect_idx(x0 + sx - 2, W);
        float v;
        if (ch < 3) v = image[((size_t)(b*3 + ch))*HW + gy*W + gx];
        else        v = edges[(size_t)b*HW + gy*W + gx];
        sg[ch][ry][sx] = v;
    }
    __syncthreads();

    float sp[5], g2[5];
    {
        float s = 0.f;
#pragma unroll
        for (int i = 0; i < 5; i++) {
            float x = (float)(i - 2);
            sp[i] = __expf(-x*x * 0.02f);    // spatial, sigma_space=5 (norm cancels)
            float g = __expf(-2.f * x*x);    // blur kernel, sigma=0.5
            g2[i] = g; s += g;
        }
        float inv = 1.f / s;
#pragma unroll
        for (int i = 0; i < 5; i++) g2[i] *= inv;
    }

    int ry = ty + 2, rx = tx + 2;
    float cr = sg[0][ry][rx], cg = sg[1][ry][rx], cb = sg[2][ry][rx], ce = sg[3][ry][rx];

    float wr[NTAP], we[NTAP];
    float sr = 0.f, se = 0.f;
#pragma unroll
    for (int dy = 0; dy < 5; dy++) {
#pragma unroll
        for (int dx = 0; dx < 5; dx++) {
            int t = dy*5 + dx;
            float d = fabsf(sg[0][ry+dy-2][rx+dx-2] - cr)
                    + fabsf(sg[1][ry+dy-2][rx+dx-2] - cg)
                    + fabsf(sg[2][ry+dy-2][rx+dx-2] - cb);
            float s2 = sp[dy] * sp[dx];
            float w  = s2 * __expf(-2.f * d * d);
            wr[t] = w; sr += w;
            float de = fabsf(sg[3][ry+dy-2][rx+dx-2] - ce);
            float w2 = s2 * __expf(-2.f * de * de);
            we[t] = w2; se += w2;
        }
    }
    float isr = 1.f / sr, ise = 1.f / se;
    int pix = b*HW + (y0 + ty)*W + (x0 + tx);
#pragma unroll
    for (int dy = 0; dy < 5; dy++) {
#pragma unroll
        for (int dx = 0; dx < 5; dx++) {
            int t = dy*5 + dx;
            g_wch[t*(NB*HW) + pix] = __float2half(g2[dy]*g2[dx] + wr[t]*isr + we[t]*ise);
        }
    }
}

// ---------------------------------------------------------------------------
// Kernel 3: one CRF iteration.
// Tile 64x8, block (32,8)=256 thr, 2 px/thread. 2 CTAs/SM (regs<=128).
// q fp16 in smem [NC][SH][SW=72], window starts at x0-4 for 8B cp.async align.
// ---------------------------------------------------------------------------
#define TX 64
#define TY 8
#define SW 72            // x0-4 .. x0+67
#define SH 12            // TY + 4
#define ROWB 144         // SW * 2 bytes
#define NCHUNK8 (NC*SH*18)   // 8B chunks (4 halves): 4536
#define NCHUNK4 (NC*SH*36)   // 4B chunks (half2):    9072

template<bool FINAL>
__global__ void __launch_bounds__(256, 2) crf_iter(const float* __restrict__ unary,
                                                   const __half* __restrict__ qin,
                                                   __half* __restrict__ qout_h,
                                                   float* __restrict__ qout_f) {
    __shared__ __half sq[NC*SH*SW];
    int tx = threadIdx.x, ty = threadIdx.y;
    int b = blockIdx.z;
    int x0 = blockIdx.x * TX, y0 = blockIdx.y * TY;
    int tid = ty * 32 + tx;

    const __half* qb = qin + (size_t)b * NC * HW;
    uint32_t sbase = (uint32_t)__cvta_generic_to_shared(sq);

    bool xInt = (blockIdx.x != 0) && (blockIdx.x != (int)gridDim.x - 1);

    if (xInt) {
#pragma unroll
        for (int it = 0; it < 18; it++) {
            int idx = tid + it*256;
            if (idx < NCHUNK8) {
                int cx  = idx % 18;
                int row = idx / 18;
                int ry  = row % SH;
                int c   = row / SH;
                int gy  = reflect_idx(y0 + ry - 2, H);
                const __half* src = qb + c*HW + gy*W + (x0 - 4 + cx*4);
                uint32_t dst = sbase + (uint32_t)(row*ROWB + cx*8);
                asm volatile("cp.async.ca.shared.global [%0], [%1], 8;"
                             :: "r"(dst), "l"(src));
            }
        }
        asm volatile("cp.async.commit_group;");
        asm volatile("cp.async.wait_group 0;" ::: "memory");
    } else {
#pragma unroll 4
        for (int it = 0; it < 36; it++) {
            int idx = tid + it*256;
            if (idx < NCHUNK4) {
                int cx  = idx % 36;
                int row = idx / 36;
                int ry  = row % SH;
                int c   = row / SH;
                int gy  = reflect_idx(y0 + ry - 2, H);
                int gxa = reflect_idx(x0 - 4 + cx*2,     W);
                int gxb = reflect_idx(x0 - 4 + cx*2 + 1, W);
                const __half* src = qb + c*HW + gy*W;
                __half2 v = __halves2half2(src[gxa], src[gxb]);
                *reinterpret_cast<__half2*>(
                    reinterpret_cast<char*>(sq) + row*ROWB + cx*4) = v;
            }
        }
    }
    __syncthreads();

    int xl  = tx * 2;
    int gx0 = x0 + xl;
    int gy  = y0 + ty;

    float acc0[NC], acc1[NC];
#pragma unroll
    for (int cc = 0; cc < NC; cc++) { acc0[cc] = 0.f; acc1[cc] = 0.f; }

    int wbase = b*HW + gy*W + gx0;
#pragma unroll
    for (int dy = 0; dy < 5; dy++) {
        float c0[5], c1[5];
#pragma unroll
        for (int dx = 0; dx < 5; dx++) {
            __half2 h = *reinterpret_cast<const __half2*>(&g_wch[(dy*5 + dx)*(NB*HW) + wbase]);
            float2 cc = __half22float2(h);
            c0[dx] = cc.x; c1[dx] = cc.y;
        }
        // window q[gx0-2 .. gx0+3] -> smem halves at [(ty+dy) row, xl+2 .. xl+7]
        const __half* rowb = sq + (ty + dy)*SW + xl + 2;
#pragma unroll
        for (int ch = 0; ch < NC; ch++) {
            const __half* rp = rowb + ch*(SH*SW);
            float2 f0 = __half22float2(*reinterpret_cast<const __half2*>(rp));
            float2 f1 = __half22float2(*reinterpret_cast<const __half2*>(rp + 2));
            float2 f2 = __half22float2(*reinterpret_cast<const __half2*>(rp + 4));
            acc0[ch] += c0[0]*f0.x + c0[1]*f0.y + c0[2]*f1.x + c0[3]*f1.y + c0[4]*f2.x;
            acc1[ch] += c1[0]*f0.y + c1[1]*f1.x + c1[2]*f1.y + c1[3]*f2.x + c1[4]*f2.y;
        }
    }

    // q_out = softmax(unary - F)   (softmax shift-invariance kills _compat colsum)
    const float* ub = unary + (size_t)b * NC * HW + gy*W + gx0;
    float s0 = 0.f, s1 = 0.f;
#pragma unroll
    for (int ch = 0; ch < NC; ch++) {
        float2 u = *reinterpret_cast<const float2*>(ub + ch*HW);
        float e0 = __expf(u.x - acc0[ch]);
        float e1 = __expf(u.y - acc1[ch]);
        acc0[ch] = e0; acc1[ch] = e1;
        s0 += e0; s1 += e1;
    }
    float i0 = 1.f / s0, i1 = 1.f / s1;
    if (FINAL) {
        float* qo = qout_f + (size_t)b * NC * HW + gy*W + gx0;
#pragma unroll
        for (int ch = 0; ch < NC; ch++) {
            float2 o; o.x = acc0[ch]*i0; o.y = acc1[ch]*i1;
            *reinterpret_cast<float2*>(qo + ch*HW) = o;
        }
    } else {
        __half* qo = qout_h + (size_t)b * NC * HW + gy*W + gx0;
#pragma unroll
        for (int ch = 0; ch < NC; ch++) {
            *reinterpret_cast<__half2*>(qo + ch*HW) =
                __floats2half2_rn(acc0[ch]*i0, acc1[ch]*i1);
        }
    }
}

// ---------------------------------------------------------------------------
extern "C" void kernel_launch(void* const* d_in, const int* in_sizes, int n_in,
                              void* d_out, int out_size) {
    const float *unary = nullptr, *image = nullptr, *edges = nullptr;
    for (int i = 0; i < n_in; i++) {
        if      (in_sizes[i] == NB*NC*HW) unary = (const float*)d_in[i];
        else if (in_sizes[i] == NB*3*HW)  image = (const float*)d_in[i];
        else if (in_sizes[i] == NB*HW)    edges = (const float*)d_in[i];
    }
    float* out = (float*)d_out;

    __half *qA = nullptr, *qB = nullptr;
    cudaGetSymbolAddress((void**)&qA, g_qA);
    cudaGetSymbolAddress((void**)&qB, g_qB);

    init_softmax<<<(NPIX + 255)/256, 256>>>(unary, qA);
    compute_weights<<<dim3(W/32, H/8, NB), dim3(32, 8)>>>(image, edges);

    dim3 gi(W/TX, H/TY, NB), bi(32, 8);
    const __half* cur = qA;
    for (int it = 0; it < 9; it++) {
        __half* dst = (cur == qA) ? qB : qA;
        crf_iter<false><<<gi, bi>>>(unary, cur, dst, nullptr);
        cur = dst;
    }
    crf_iter<true><<<gi, bi>>>(unary, cur, nullptr, out);
}